// round 2
// baseline (speedup 1.0000x reference)
#include <cuda_runtime.h>
#include <math.h>

// Problem constants
constexpr int BSZ = 64;     // batch
constexpr int SEQ = 512;    // sequence length
constexpr int IN  = 512;    // input dim
constexpr int HD  = 1024;   // hidden dim
constexpr int G4  = 4 * HD; // 4096 gate columns

// Scratch: xg = x @ Xcat + bcat, layout [m = b*SEQ + t][gate*HD + j]
__device__ float g_xg[(size_t)BSZ * SEQ * G4];   // 512 MB
__device__ float g_h[BSZ * HD];
__device__ float g_c[BSZ * HD];

// ---------------------------------------------------------------------------
// Zero h, c state
// ---------------------------------------------------------------------------
__global__ void init_state_kernel() {
    int i = blockIdx.x * blockDim.x + threadIdx.x;
    if (i < BSZ * HD) {
        g_h[i] = 0.0f;
        g_c[i] = 0.0f;
    }
}

// ---------------------------------------------------------------------------
// Input projection: xg[m, gate*HD + n] = sum_k x[m,k] * Xg[k,n] + bg[n]
// Tiles: BM=64, BN=64, BK=16, 256 threads, 4x4 register blocking.
// grid = (HD/64, M/64, 4 gates)
// ---------------------------------------------------------------------------
__global__ __launch_bounds__(256, 4)
void xproj_kernel(const float* __restrict__ x,
                  const float* __restrict__ X1, const float* __restrict__ X2,
                  const float* __restrict__ X3, const float* __restrict__ X4,
                  const float* __restrict__ b1, const float* __restrict__ b2,
                  const float* __restrict__ b3, const float* __restrict__ b4)
{
    const int gate = blockIdx.z;
    const float* __restrict__ Xg = (gate == 0) ? X1 : (gate == 1) ? X2 : (gate == 2) ? X3 : X4;
    const float* __restrict__ bg = (gate == 0) ? b1 : (gate == 1) ? b2 : (gate == 2) ? b3 : b4;

    const int m0 = blockIdx.y * 64;
    const int n0 = blockIdx.x * 64;

    __shared__ float As[16][64];  // [k][m]
    __shared__ float Bs[16][64];  // [k][n]

    const int tid = threadIdx.x;
    const int tx = tid & 15;      // 0..15 -> 4 n-cols each
    const int ty = tid >> 4;      // 0..15 -> 4 m-rows each

    float acc[4][4];
    #pragma unroll
    for (int r = 0; r < 4; r++)
        #pragma unroll
        for (int c = 0; c < 4; c++) acc[r][c] = 0.0f;

    for (int k0 = 0; k0 < IN; k0 += 16) {
        // Load A tile 64x16 (x), one float4 per thread, transpose to [k][m]
        {
            int row = tid >> 2;        // 0..63
            int kq  = tid & 3;         // 0..3 (float4 index within 16 k)
            float4 v = *(const float4*)(x + (size_t)(m0 + row) * IN + k0 + kq * 4);
            As[kq * 4 + 0][row] = v.x;
            As[kq * 4 + 1][row] = v.y;
            As[kq * 4 + 2][row] = v.z;
            As[kq * 4 + 3][row] = v.w;
        }
        // Load B tile 16x64 (Xg), one float4 per thread, natural layout
        {
            int kr = tid >> 4;         // 0..15
            int nq = tid & 15;         // 0..15
            float4 v = *(const float4*)(Xg + (size_t)(k0 + kr) * HD + n0 + nq * 4);
            *(float4*)&Bs[kr][nq * 4] = v;
        }
        __syncthreads();

        #pragma unroll
        for (int k = 0; k < 16; k++) {
            float a[4], b[4];
            #pragma unroll
            for (int r = 0; r < 4; r++) a[r] = As[k][ty * 4 + r];
            #pragma unroll
            for (int c = 0; c < 4; c++) b[c] = Bs[k][tx * 4 + c];
            #pragma unroll
            for (int r = 0; r < 4; r++)
                #pragma unroll
                for (int c = 0; c < 4; c++)
                    acc[r][c] = fmaf(a[r], b[c], acc[r][c]);
        }
        __syncthreads();
    }

    // Epilogue: add bias, store to g_xg
    #pragma unroll
    for (int r = 0; r < 4; r++) {
        int m = m0 + ty * 4 + r;
        size_t base = (size_t)m * G4 + (size_t)gate * HD + n0;
        #pragma unroll
        for (int c = 0; c < 4; c++) {
            int n = tx * 4 + c;
            g_xg[base + n] = acc[r][c] + bg[n0 + n];
        }
    }
}

// ---------------------------------------------------------------------------
// One LSTM timestep, fully fused:
//   g = xg[:, t, :] + h @ Hcat ; gates ; c,h update ; h -> out
// grid = 128 CTAs, each handles all 64 batch rows x (4 gates x 8 j-columns).
// 128 threads, 4x4 register blocking over the 64x32 tile.
// ---------------------------------------------------------------------------
__global__ __launch_bounds__(128, 8)
void lstm_step_kernel(int t,
                      const float* __restrict__ H1, const float* __restrict__ H2,
                      const float* __restrict__ H3, const float* __restrict__ H4,
                      float* __restrict__ out)
{
    const int j0 = blockIdx.x * 8;   // 8 hidden columns, shared across 4 gates

    __shared__ float As[32][64];     // h chunk   [k][b]   8 KB
    __shared__ float Bs[32][32];     // Hcat cols [k][c]   4 KB
    __shared__ float Gs[64][33];     // g tile    [b][c]   padded, 8.25 KB

    const int tid = threadIdx.x;
    const int tx = tid & 7;          // 0..7  -> 4 cols each (within one gate block)
    const int ty = tid >> 3;         // 0..15 -> 4 rows each

    float acc[4][4];
    #pragma unroll
    for (int r = 0; r < 4; r++)
        #pragma unroll
        for (int c = 0; c < 4; c++) acc[r][c] = 0.0f;

    // B loading role for this thread: one (k, gate) pair per chunk
    const int bk   = tid >> 2;       // 0..31
    const int bg_  = tid & 3;        // gate 0..3
    const float* __restrict__ Hg =
        (bg_ == 0) ? H1 : (bg_ == 1) ? H2 : (bg_ == 2) ? H3 : H4;

    for (int k0 = 0; k0 < HD; k0 += 32) {
        // Load A: 64 x 32 chunk of h (float4 along k, transpose-store)
        #pragma unroll
        for (int i = 0; i < 4; i++) {
            int q   = tid + 128 * i;   // 0..511
            int row = q >> 3;          // 0..63
            int kq  = q & 7;           // float4 index
            float4 v = *(const float4*)(g_h + row * HD + k0 + kq * 4);
            As[kq * 4 + 0][row] = v.x;
            As[kq * 4 + 1][row] = v.y;
            As[kq * 4 + 2][row] = v.z;
            As[kq * 4 + 3][row] = v.w;
        }
        // Load B: 32 k-rows x (4 gates x 8 j) columns
        {
            const float* src = Hg + (size_t)(k0 + bk) * HD + j0;
            float4 v0 = *(const float4*)(src);
            float4 v1 = *(const float4*)(src + 4);
            *(float4*)&Bs[bk][bg_ * 8]     = v0;
            *(float4*)&Bs[bk][bg_ * 8 + 4] = v1;
        }
        __syncthreads();

        #pragma unroll
        for (int k = 0; k < 32; k++) {
            float a[4], b[4];
            #pragma unroll
            for (int r = 0; r < 4; r++) a[r] = As[k][ty * 4 + r];
            #pragma unroll
            for (int c = 0; c < 4; c++) b[c] = Bs[k][tx * 4 + c];
            #pragma unroll
            for (int r = 0; r < 4; r++)
                #pragma unroll
                for (int c = 0; c < 4; c++)
                    acc[r][c] = fmaf(a[r], b[c], acc[r][c]);
        }
        __syncthreads();
    }

    // Stage g tile to SMEM so each thread can gather all 4 gates per (b, j)
    #pragma unroll
    for (int r = 0; r < 4; r++)
        #pragma unroll
        for (int c = 0; c < 4; c++)
            Gs[ty * 4 + r][tx * 4 + c] = acc[r][c];
    __syncthreads();

    // Epilogue: 512 (b, j) pairs in this tile, 4 per thread
    #pragma unroll
    for (int i = 0; i < 4; i++) {
        int p  = tid + 128 * i;     // 0..511
        int b  = p >> 3;            // 0..63
        int jj = p & 7;             // 0..7
        int j  = j0 + jj;

        size_t xbase = ((size_t)b * SEQ + t) * G4 + j;
        float gf = Gs[b][0 * 8 + jj] + g_xg[xbase];            // forget
        float gi = Gs[b][1 * 8 + jj] + g_xg[xbase + HD];       // input
        float gc = Gs[b][2 * 8 + jj] + g_xg[xbase + 2 * HD];   // candidate
        float go = Gs[b][3 * 8 + jj] + g_xg[xbase + 3 * HD];   // output

        float s1 = 1.0f / (1.0f + expf(-gf));
        float s2 = 1.0f / (1.0f + expf(-gi));
        float t1 = tanhf(gc);
        float s3 = 1.0f / (1.0f + expf(-go));

        int   hidx = b * HD + j;
        float cnew = g_c[hidx] * s1 + s2 * t1;
        float hnew = tanhf(cnew) * s3;

        g_c[hidx] = cnew;
        g_h[hidx] = hnew;
        out[((size_t)b * SEQ + t) * HD + j] = hnew;
    }
}

// ---------------------------------------------------------------------------
// Launch
// ---------------------------------------------------------------------------
extern "C" void kernel_launch(void* const* d_in, const int* in_sizes, int n_in,
                              void* d_out, int out_size)
{
    const float* x  = (const float*)d_in[0];
    const float* X1 = (const float*)d_in[1];
    const float* H1 = (const float*)d_in[2];
    const float* b1 = (const float*)d_in[3];
    const float* X2 = (const float*)d_in[4];
    const float* H2 = (const float*)d_in[5];
    const float* b2 = (const float*)d_in[6];
    const float* X3 = (const float*)d_in[7];
    const float* H3 = (const float*)d_in[8];
    const float* b3 = (const float*)d_in[9];
    const float* X4 = (const float*)d_in[10];
    const float* H4 = (const float*)d_in[11];
    const float* b4 = (const float*)d_in[12];
    float* out = (float*)d_out;

    // Zero recurrent state
    init_state_kernel<<<(BSZ * HD + 255) / 256, 256>>>();

    // Input projection: xg = x @ Xcat + bcat
    dim3 grid_x(HD / 64, (BSZ * SEQ) / 64, 4);
    xproj_kernel<<<grid_x, 256>>>(x, X1, X2, X3, X4, b1, b2, b3, b4);

    // Sequential recurrence
    for (int t = 0; t < SEQ; t++) {
        lstm_step_kernel<<<HD / 8, 128>>>(t, H1, H2, H3, H4, out);
    }
}

// round 3
// speedup vs baseline: 1.0017x; 1.0017x over previous
#include <cuda_runtime.h>
#include <math.h>

// Problem constants
constexpr int BSZ = 64;     // batch
constexpr int SEQ = 512;    // sequence length
constexpr int IN  = 512;    // input dim
constexpr int HD  = 1024;   // hidden dim
constexpr int G4  = 4 * HD; // 4096 gate columns

// Scratch: xg = x @ Xcat + bcat, layout [m = b*SEQ + t][gate*HD + j]
__device__ float g_xg[(size_t)BSZ * SEQ * G4];   // 512 MB
__device__ float g_h[BSZ * HD];
__device__ float g_c[BSZ * HD];

// ---------------------------------------------------------------------------
// Zero h, c state
// ---------------------------------------------------------------------------
__global__ void init_state_kernel() {
    int i = blockIdx.x * blockDim.x + threadIdx.x;
    if (i < BSZ * HD) {
        g_h[i] = 0.0f;
        g_c[i] = 0.0f;
    }
}

// ---------------------------------------------------------------------------
// Input projection: xg[m, gate*HD + n] = sum_k x[m,k] * Xg[k,n] + bg[n]
// Tiles: BM=64, BN=64, BK=16, 256 threads, 4x4 register blocking.
// grid = (HD/64, M/64, 4 gates)
// ---------------------------------------------------------------------------
__global__ __launch_bounds__(256, 4)
void xproj_kernel(const float* __restrict__ x,
                  const float* __restrict__ X1, const float* __restrict__ X2,
                  const float* __restrict__ X3, const float* __restrict__ X4,
                  const float* __restrict__ b1, const float* __restrict__ b2,
                  const float* __restrict__ b3, const float* __restrict__ b4)
{
    const int gate = blockIdx.z;
    const float* __restrict__ Xg = (gate == 0) ? X1 : (gate == 1) ? X2 : (gate == 2) ? X3 : X4;
    const float* __restrict__ bg = (gate == 0) ? b1 : (gate == 1) ? b2 : (gate == 2) ? b3 : b4;

    const int m0 = blockIdx.y * 64;
    const int n0 = blockIdx.x * 64;

    __shared__ float As[16][64];  // [k][m]
    __shared__ float Bs[16][64];  // [k][n]

    const int tid = threadIdx.x;
    const int tx = tid & 15;      // 0..15 -> 4 n-cols each
    const int ty = tid >> 4;      // 0..15 -> 4 m-rows each

    float acc[4][4];
    #pragma unroll
    for (int r = 0; r < 4; r++)
        #pragma unroll
        for (int c = 0; c < 4; c++) acc[r][c] = 0.0f;

    for (int k0 = 0; k0 < IN; k0 += 16) {
        // Load A tile 64x16 (x), one float4 per thread, transpose to [k][m]
        {
            int row = tid >> 2;        // 0..63
            int kq  = tid & 3;         // 0..3 (float4 index within 16 k)
            float4 v = *(const float4*)(x + (size_t)(m0 + row) * IN + k0 + kq * 4);
            As[kq * 4 + 0][row] = v.x;
            As[kq * 4 + 1][row] = v.y;
            As[kq * 4 + 2][row] = v.z;
            As[kq * 4 + 3][row] = v.w;
        }
        // Load B tile 16x64 (Xg), one float4 per thread, natural layout
        {
            int kr = tid >> 4;         // 0..15
            int nq = tid & 15;         // 0..15
            float4 v = *(const float4*)(Xg + (size_t)(k0 + kr) * HD + n0 + nq * 4);
            *(float4*)&Bs[kr][nq * 4] = v;
        }
        __syncthreads();

        #pragma unroll
        for (int k = 0; k < 16; k++) {
            float a[4], b[4];
            #pragma unroll
            for (int r = 0; r < 4; r++) a[r] = As[k][ty * 4 + r];
            #pragma unroll
            for (int c = 0; c < 4; c++) b[c] = Bs[k][tx * 4 + c];
            #pragma unroll
            for (int r = 0; r < 4; r++)
                #pragma unroll
                for (int c = 0; c < 4; c++)
                    acc[r][c] = fmaf(a[r], b[c], acc[r][c]);
        }
        __syncthreads();
    }

    // Epilogue: add bias, store to g_xg
    #pragma unroll
    for (int r = 0; r < 4; r++) {
        int m = m0 + ty * 4 + r;
        size_t base = (size_t)m * G4 + (size_t)gate * HD + n0;
        #pragma unroll
        for (int c = 0; c < 4; c++) {
            int n = tx * 4 + c;
            g_xg[base + n] = acc[r][c] + bg[n0 + n];
        }
    }
}

// ---------------------------------------------------------------------------
// One LSTM timestep, fully fused:
//   g = xg[:, t, :] + h @ Hcat ; gates ; c,h update ; h -> out
// grid = 128 CTAs, each handles all 64 batch rows x (4 gates x 8 j-columns).
// 128 threads, 4x4 register blocking over the 64x32 tile.
// ---------------------------------------------------------------------------
__global__ __launch_bounds__(128, 8)
void lstm_step_kernel(int t,
                      const float* __restrict__ H1, const float* __restrict__ H2,
                      const float* __restrict__ H3, const float* __restrict__ H4,
                      float* __restrict__ out)
{
    const int j0 = blockIdx.x * 8;   // 8 hidden columns, shared across 4 gates

    __shared__ float As[32][64];     // h chunk   [k][b]   8 KB
    __shared__ float Bs[32][32];     // Hcat cols [k][c]   4 KB
    __shared__ float Gs[64][33];     // g tile    [b][c]   padded, 8.25 KB

    const int tid = threadIdx.x;
    const int tx = tid & 7;          // 0..7  -> 4 cols each (within one gate block)
    const int ty = tid >> 3;         // 0..15 -> 4 rows each

    float acc[4][4];
    #pragma unroll
    for (int r = 0; r < 4; r++)
        #pragma unroll
        for (int c = 0; c < 4; c++) acc[r][c] = 0.0f;

    // B loading role for this thread: one (k, gate) pair per chunk
    const int bk   = tid >> 2;       // 0..31
    const int bg_  = tid & 3;        // gate 0..3
    const float* __restrict__ Hg =
        (bg_ == 0) ? H1 : (bg_ == 1) ? H2 : (bg_ == 2) ? H3 : H4;

    for (int k0 = 0; k0 < HD; k0 += 32) {
        // Load A: 64 x 32 chunk of h (float4 along k, transpose-store)
        #pragma unroll
        for (int i = 0; i < 4; i++) {
            int q   = tid + 128 * i;   // 0..511
            int row = q >> 3;          // 0..63
            int kq  = q & 7;           // float4 index
            float4 v = *(const float4*)(g_h + row * HD + k0 + kq * 4);
            As[kq * 4 + 0][row] = v.x;
            As[kq * 4 + 1][row] = v.y;
            As[kq * 4 + 2][row] = v.z;
            As[kq * 4 + 3][row] = v.w;
        }
        // Load B: 32 k-rows x (4 gates x 8 j) columns
        {
            const float* src = Hg + (size_t)(k0 + bk) * HD + j0;
            float4 v0 = *(const float4*)(src);
            float4 v1 = *(const float4*)(src + 4);
            *(float4*)&Bs[bk][bg_ * 8]     = v0;
            *(float4*)&Bs[bk][bg_ * 8 + 4] = v1;
        }
        __syncthreads();

        #pragma unroll
        for (int k = 0; k < 32; k++) {
            float a[4], b[4];
            #pragma unroll
            for (int r = 0; r < 4; r++) a[r] = As[k][ty * 4 + r];
            #pragma unroll
            for (int c = 0; c < 4; c++) b[c] = Bs[k][tx * 4 + c];
            #pragma unroll
            for (int r = 0; r < 4; r++)
                #pragma unroll
                for (int c = 0; c < 4; c++)
                    acc[r][c] = fmaf(a[r], b[c], acc[r][c]);
        }
        __syncthreads();
    }

    // Stage g tile to SMEM so each thread can gather all 4 gates per (b, j)
    #pragma unroll
    for (int r = 0; r < 4; r++)
        #pragma unroll
        for (int c = 0; c < 4; c++)
            Gs[ty * 4 + r][tx * 4 + c] = acc[r][c];
    __syncthreads();

    // Epilogue: 512 (b, j) pairs in this tile, 4 per thread
    #pragma unroll
    for (int i = 0; i < 4; i++) {
        int p  = tid + 128 * i;     // 0..511
        int b  = p >> 3;            // 0..63
        int jj = p & 7;             // 0..7
        int j  = j0 + jj;

        size_t xbase = ((size_t)b * SEQ + t) * G4 + j;
        float gf = Gs[b][0 * 8 + jj] + g_xg[xbase];            // forget
        float gi = Gs[b][1 * 8 + jj] + g_xg[xbase + HD];       // input
        float gc = Gs[b][2 * 8 + jj] + g_xg[xbase + 2 * HD];   // candidate
        float go = Gs[b][3 * 8 + jj] + g_xg[xbase + 3 * HD];   // output

        float s1 = 1.0f / (1.0f + expf(-gf));
        float s2 = 1.0f / (1.0f + expf(-gi));
        float t1 = tanhf(gc);
        float s3 = 1.0f / (1.0f + expf(-go));

        int   hidx = b * HD + j;
        float cnew = g_c[hidx] * s1 + s2 * t1;
        float hnew = tanhf(cnew) * s3;

        g_c[hidx] = cnew;
        g_h[hidx] = hnew;
        out[((size_t)b * SEQ + t) * HD + j] = hnew;
    }
}

// ---------------------------------------------------------------------------
// Launch
// ---------------------------------------------------------------------------
extern "C" void kernel_launch(void* const* d_in, const int* in_sizes, int n_in,
                              void* d_out, int out_size)
{
    const float* x  = (const float*)d_in[0];
    const float* X1 = (const float*)d_in[1];
    const float* H1 = (const float*)d_in[2];
    const float* b1 = (const float*)d_in[3];
    const float* X2 = (const float*)d_in[4];
    const float* H2 = (const float*)d_in[5];
    const float* b2 = (const float*)d_in[6];
    const float* X3 = (const float*)d_in[7];
    const float* H3 = (const float*)d_in[8];
    const float* b3 = (const float*)d_in[9];
    const float* X4 = (const float*)d_in[10];
    const float* H4 = (const float*)d_in[11];
    const float* b4 = (const float*)d_in[12];
    float* out = (float*)d_out;

    // Zero recurrent state
    init_state_kernel<<<(BSZ * HD + 255) / 256, 256>>>();

    // Input projection: xg = x @ Xcat + bcat
    dim3 grid_x(HD / 64, (BSZ * SEQ) / 64, 4);
    xproj_kernel<<<grid_x, 256>>>(x, X1, X2, X3, X4, b1, b2, b3, b4);

    // Sequential recurrence
    for (int t = 0; t < SEQ; t++) {
        lstm_step_kernel<<<HD / 8, 128>>>(t, H1, H2, H3, H4, out);
    }
}

// round 4
// speedup vs baseline: 1.9341x; 1.9309x over previous
#include <cuda_runtime.h>
#include <math.h>

// Problem constants
constexpr int BSZ = 64;     // batch
constexpr int SEQ = 512;    // sequence length
constexpr int IN  = 512;    // input dim
constexpr int HD  = 1024;   // hidden dim
constexpr int G4  = 4 * HD; // 4096 gate columns

constexpr int NCTAS = 128;  // persistent grid (1 CTA per SM, 148 SMs available)
constexpr int NTHR  = 128;

// Scratch: xg = x @ Xcat + bcat, layout [m = b*SEQ + t][gate*HD + j]
__device__ float g_xg[(size_t)BSZ * SEQ * G4];   // 512 MB
__device__ float g_h[BSZ * HD];
__device__ unsigned g_count;
__device__ unsigned g_phase;

// Dynamic SMEM layout (bytes):
//   Bs: [1024][32] floats  @ 0        (131072 B)  -- Hcat slice, loaded once
//   As: [2][64][36] floats @ 131072   (18432 B)   -- double-buffered h chunks
//   Gs: [64][36] floats    @ 149504   (9216 B)    -- g tile for epilogue
constexpr int SMEM_BS    = 0;
constexpr int SMEM_AS    = 131072;
constexpr int SMEM_GS    = 149504;
constexpr int SMEM_TOTAL = 149504 + 9216;          // 158720 B

// ---------------------------------------------------------------------------
// Zero h and barrier state
// ---------------------------------------------------------------------------
__global__ void init_state_kernel() {
    int i = blockIdx.x * blockDim.x + threadIdx.x;
    if (i < BSZ * HD) g_h[i] = 0.0f;
    if (i == 0) { g_count = 0u; g_phase = 0u; }
}

// ---------------------------------------------------------------------------
// Input projection: xg[m, gate*HD + n] = sum_k x[m,k] * Xg[k,n] + bg[n]
// (unchanged from baseline; one big parallel GEMM, not on the critical path)
// ---------------------------------------------------------------------------
__global__ __launch_bounds__(256, 4)
void xproj_kernel(const float* __restrict__ x,
                  const float* __restrict__ X1, const float* __restrict__ X2,
                  const float* __restrict__ X3, const float* __restrict__ X4,
                  const float* __restrict__ b1, const float* __restrict__ b2,
                  const float* __restrict__ b3, const float* __restrict__ b4)
{
    const int gate = blockIdx.z;
    const float* __restrict__ Xg = (gate == 0) ? X1 : (gate == 1) ? X2 : (gate == 2) ? X3 : X4;
    const float* __restrict__ bg = (gate == 0) ? b1 : (gate == 1) ? b2 : (gate == 2) ? b3 : b4;

    const int m0 = blockIdx.y * 64;
    const int n0 = blockIdx.x * 64;

    __shared__ float As[16][64];
    __shared__ float Bs[16][64];

    const int tid = threadIdx.x;
    const int tx = tid & 15;
    const int ty = tid >> 4;

    float acc[4][4];
    #pragma unroll
    for (int r = 0; r < 4; r++)
        #pragma unroll
        for (int c = 0; c < 4; c++) acc[r][c] = 0.0f;

    for (int k0 = 0; k0 < IN; k0 += 16) {
        {
            int row = tid >> 2;
            int kq  = tid & 3;
            float4 v = *(const float4*)(x + (size_t)(m0 + row) * IN + k0 + kq * 4);
            As[kq * 4 + 0][row] = v.x;
            As[kq * 4 + 1][row] = v.y;
            As[kq * 4 + 2][row] = v.z;
            As[kq * 4 + 3][row] = v.w;
        }
        {
            int kr = tid >> 4;
            int nq = tid & 15;
            float4 v = *(const float4*)(Xg + (size_t)(k0 + kr) * HD + n0 + nq * 4);
            *(float4*)&Bs[kr][nq * 4] = v;
        }
        __syncthreads();

        #pragma unroll
        for (int k = 0; k < 16; k++) {
            float a[4], b[4];
            #pragma unroll
            for (int r = 0; r < 4; r++) a[r] = As[k][ty * 4 + r];
            #pragma unroll
            for (int c = 0; c < 4; c++) b[c] = Bs[k][tx * 4 + c];
            #pragma unroll
            for (int r = 0; r < 4; r++)
                #pragma unroll
                for (int c = 0; c < 4; c++)
                    acc[r][c] = fmaf(a[r], b[c], acc[r][c]);
        }
        __syncthreads();
    }

    #pragma unroll
    for (int r = 0; r < 4; r++) {
        int m = m0 + ty * 4 + r;
        size_t base = (size_t)m * G4 + (size_t)gate * HD + n0;
        #pragma unroll
        for (int c = 0; c < 4; c++) {
            int n = tx * 4 + c;
            g_xg[base + n] = acc[r][c] + bg[n0 + n];
        }
    }
}

// ---------------------------------------------------------------------------
// Software grid barrier (all NCTAS CTAs resident by construction: 1 CTA/SM)
// ---------------------------------------------------------------------------
__device__ __forceinline__ void grid_sync(unsigned target) {
    __syncthreads();
    if (threadIdx.x == 0) {
        __threadfence();                      // publish h/out stores
        if (atomicAdd(&g_count, 1u) == NCTAS - 1) {
            atomicExch(&g_count, 0u);
            __threadfence();
            atomicExch(&g_phase, target);
        } else {
            while (atomicAdd(&g_phase, 0u) < target) { __nanosleep(64); }
        }
        __threadfence();                      // CCTL.IVALL: invalidate L1 so fresh h is read
    }
    __syncthreads();
}

// ---------------------------------------------------------------------------
// Persistent recurrence kernel: all 512 timesteps in one launch.
// Each CTA owns 8 hidden columns (x 4 gates = 32 N-cols) for all 64 batch rows.
//  - Hcat slice cached in SMEM once (128 KB), reused for all steps
//  - c state in registers (exclusive ownership)
//  - h streamed through double-buffered SMEM, LDG prefetch 2 chunks ahead
//  - fma.rn.f32x2 packed math (2 FLOPs/lane/instr)
// ---------------------------------------------------------------------------
__global__ void __launch_bounds__(NTHR, 1)
lstm_persistent_kernel(const float* __restrict__ H1, const float* __restrict__ H2,
                       const float* __restrict__ H3, const float* __restrict__ H4,
                       float* __restrict__ out)
{
    extern __shared__ char smem[];
    float* Bs = (float*)(smem + SMEM_BS);   // [k][c], c = gate*8 + jj, stride 32
    float* As = (float*)(smem + SMEM_AS);   // [buf][row][kk], stride 36, buf stride 2304
    float* Gs = (float*)(smem + SMEM_GS);   // [row][col], stride 36

    const int tid = threadIdx.x;
    const int tx  = tid & 7;                // 4 tile-cols each
    const int ty  = tid >> 3;               // 4 tile-rows each
    const int j0  = blockIdx.x * 8;

    // ---- Load Hcat slice (32 cols x 1024 k) into SMEM once ----
    {
        const int bk  = tid >> 2;           // 0..31
        const int bgt = tid & 3;            // gate
        const float* __restrict__ Hg = (bgt == 0) ? H1 : (bgt == 1) ? H2 : (bgt == 2) ? H3 : H4;
        for (int k0 = 0; k0 < HD; k0 += 32) {
            const float* src = Hg + (size_t)(k0 + bk) * HD + j0;
            float4 v0 = *(const float4*)(src);
            float4 v1 = *(const float4*)(src + 4);
            *(float4*)&Bs[(k0 + bk) * 32 + bgt * 8]     = v0;
            *(float4*)&Bs[(k0 + bk) * 32 + bgt * 8 + 4] = v1;
        }
    }

    const unsigned bs_u = (unsigned)__cvta_generic_to_shared(Bs);

    // ---- Per-thread epilogue slots: 4 (b, j) pairs, fixed for all steps ----
    const float* xptr[4];
    float*       hptr[4];
    float*       optr[4];
    int          goff[4];                   // Gs base offset = b*36 + jj
    float        c_reg[4] = {0.f, 0.f, 0.f, 0.f};
    #pragma unroll
    for (int i = 0; i < 4; i++) {
        int p  = tid + NTHR * i;            // 0..511
        int b  = p >> 3;
        int jj = p & 7;
        int j  = j0 + jj;
        xptr[i] = g_xg + (size_t)b * SEQ * G4 + j;
        hptr[i] = g_h + b * HD + j;
        optr[i] = out + (size_t)b * SEQ * HD + j;
        goff[i] = b * 36 + jj;
    }

    // ---- A-staging slots: 4 float4 per thread per 64x32 chunk ----
    int aoff_g[4];                          // g_h float offset (row*HD + kq*4)
    int aoff_s[4];                          // As float offset (row*36 + kq*4)
    #pragma unroll
    for (int i = 0; i < 4; i++) {
        int q   = tid + NTHR * i;           // 0..511
        int row = q >> 3;                   // 0..63
        int kq  = q & 7;                    // 0..7
        aoff_g[i] = row * HD + kq * 4;
        aoff_s[i] = row * 36 + kq * 4;
    }

    __syncthreads();                        // Bs ready

    for (int t = 0; t < SEQ; t++) {
        // ---- Prefetch xg (DRAM) — hides under the K loop ----
        float xf[4], xi[4], xc[4], xo[4];
        const size_t toff = (size_t)t * G4;
        #pragma unroll
        for (int i = 0; i < 4; i++) {
            const float* xp = xptr[i] + toff;
            xf[i] = __ldg(xp);
            xi[i] = __ldg(xp + HD);
            xc[i] = __ldg(xp + 2 * HD);
            xo[i] = __ldg(xp + 3 * HD);
        }

        unsigned long long acc0[4] = {0ull, 0ull, 0ull, 0ull};  // cols tx*4+0,1
        unsigned long long acc1[4] = {0ull, 0ull, 0ull, 0ull};  // cols tx*4+2,3

        // ---- Prologue: stage chunk 0, prefetch chunk 1 ----
        float4 v[4];
        #pragma unroll
        for (int i = 0; i < 4; i++) v[i] = *(const float4*)(g_h + aoff_g[i]);
        #pragma unroll
        for (int i = 0; i < 4; i++) *(float4*)&As[aoff_s[i]] = v[i];
        #pragma unroll
        for (int i = 0; i < 4; i++) v[i] = *(const float4*)(g_h + aoff_g[i] + 32);
        __syncthreads();

        for (int ch = 0; ch < 32; ch++) {
            // Stage chunk ch+1 into the other buffer (readers done: sync at end of ch-1)
            if (ch + 1 < 32) {
                const int nb = ((ch + 1) & 1) * 2304;
                #pragma unroll
                for (int i = 0; i < 4; i++) *(float4*)&As[nb + aoff_s[i]] = v[i];
            }
            // Prefetch chunk ch+2 from global
            if (ch + 2 < 32) {
                const int gk = (ch + 2) * 32;
                #pragma unroll
                for (int i = 0; i < 4; i++) v[i] = *(const float4*)(g_h + aoff_g[i] + gk);
            }

            const float* Ab = As + (ch & 1) * 2304;
            unsigned baddr = bs_u + (unsigned)(ch * 32 * 32 + tx * 4) * 4u;

            #pragma unroll
            for (int kk = 0; kk < 32; kk++) {
                unsigned long long b01, b23;
                asm volatile("ld.shared.v2.b64 {%0,%1},[%2];"
                             : "=l"(b01), "=l"(b23) : "r"(baddr));
                baddr += 128;

                float a0 = Ab[(ty * 4 + 0) * 36 + kk];
                float a1 = Ab[(ty * 4 + 1) * 36 + kk];
                float a2 = Ab[(ty * 4 + 2) * 36 + kk];
                float a3 = Ab[(ty * 4 + 3) * 36 + kk];

                unsigned long long aa0, aa1, aa2, aa3;
                asm("mov.b64 %0,{%1,%1};" : "=l"(aa0) : "f"(a0));
                asm("mov.b64 %0,{%1,%1};" : "=l"(aa1) : "f"(a1));
                asm("mov.b64 %0,{%1,%1};" : "=l"(aa2) : "f"(a2));
                asm("mov.b64 %0,{%1,%1};" : "=l"(aa3) : "f"(a3));

                asm("fma.rn.f32x2 %0,%1,%2,%0;" : "+l"(acc0[0]) : "l"(aa0), "l"(b01));
                asm("fma.rn.f32x2 %0,%1,%2,%0;" : "+l"(acc1[0]) : "l"(aa0), "l"(b23));
                asm("fma.rn.f32x2 %0,%1,%2,%0;" : "+l"(acc0[1]) : "l"(aa1), "l"(b01));
                asm("fma.rn.f32x2 %0,%1,%2,%0;" : "+l"(acc1[1]) : "l"(aa1), "l"(b23));
                asm("fma.rn.f32x2 %0,%1,%2,%0;" : "+l"(acc0[2]) : "l"(aa2), "l"(b01));
                asm("fma.rn.f32x2 %0,%1,%2,%0;" : "+l"(acc1[2]) : "l"(aa2), "l"(b23));
                asm("fma.rn.f32x2 %0,%1,%2,%0;" : "+l"(acc0[3]) : "l"(aa3), "l"(b01));
                asm("fma.rn.f32x2 %0,%1,%2,%0;" : "+l"(acc1[3]) : "l"(aa3), "l"(b23));
            }
            __syncthreads();
        }

        // ---- Stage g tile into Gs so epilogue threads can gather 4 gates ----
        #pragma unroll
        for (int r = 0; r < 4; r++) {
            float f0, f1, f2, f3;
            asm("mov.b64 {%0,%1},%2;" : "=f"(f0), "=f"(f1) : "l"(acc0[r]));
            asm("mov.b64 {%0,%1},%2;" : "=f"(f2), "=f"(f3) : "l"(acc1[r]));
            float4 g4v = make_float4(f0, f1, f2, f3);
            *(float4*)&Gs[(ty * 4 + r) * 36 + tx * 4] = g4v;
        }
        __syncthreads();

        // ---- Epilogue: gates, c/h update, output ----
        #pragma unroll
        for (int i = 0; i < 4; i++) {
            const int go_ = goff[i];
            float gf = Gs[go_ +  0] + xf[i];
            float gi = Gs[go_ +  8] + xi[i];
            float gc = Gs[go_ + 16] + xc[i];
            float gg = Gs[go_ + 24] + xo[i];

            float s1 = 1.0f / (1.0f + expf(-gf));
            float s2 = 1.0f / (1.0f + expf(-gi));
            float t1 = tanhf(gc);
            float s3 = 1.0f / (1.0f + expf(-gg));

            c_reg[i] = c_reg[i] * s1 + s2 * t1;
            float hnew = tanhf(c_reg[i]) * s3;

            *hptr[i] = hnew;
            optr[i][(size_t)t * HD] = hnew;
        }

        // ---- Grid-wide barrier before next step reads updated h ----
        if (t + 1 < SEQ) grid_sync((unsigned)(t + 1));
    }
}

// ---------------------------------------------------------------------------
// Launch
// ---------------------------------------------------------------------------
extern "C" void kernel_launch(void* const* d_in, const int* in_sizes, int n_in,
                              void* d_out, int out_size)
{
    const float* x  = (const float*)d_in[0];
    const float* X1 = (const float*)d_in[1];
    const float* H1 = (const float*)d_in[2];
    const float* b1 = (const float*)d_in[3];
    const float* X2 = (const float*)d_in[4];
    const float* H2 = (const float*)d_in[5];
    const float* b2 = (const float*)d_in[6];
    const float* X3 = (const float*)d_in[7];
    const float* H3 = (const float*)d_in[8];
    const float* b3 = (const float*)d_in[9];
    const float* X4 = (const float*)d_in[10];
    const float* H4 = (const float*)d_in[11];
    const float* b4 = (const float*)d_in[12];
    float* out = (float*)d_out;

    cudaFuncSetAttribute(lstm_persistent_kernel,
                         cudaFuncAttributeMaxDynamicSharedMemorySize, SMEM_TOTAL);

    // Zero recurrent state + barrier
    init_state_kernel<<<(BSZ * HD + 255) / 256, 256>>>();

    // Input projection: xg = x @ Xcat + bcat
    dim3 grid_x(HD / 64, (BSZ * SEQ) / 64, 4);
    xproj_kernel<<<grid_x, 256>>>(x, X1, X2, X3, X4, b1, b2, b3, b4);

    // Persistent recurrence: all 512 steps in one kernel
    lstm_persistent_kernel<<<NCTAS, NTHR, SMEM_TOTAL>>>(H1, H2, H3, H4, out);
}